// round 6
// baseline (speedup 1.0000x reference)
#include <cuda_runtime.h>
#include <math_constants.h>

#define DD   128
#define HH   4
#define RNUM 2000
#define MAXM 768
#define NCPY 32
#define XST  132

// ---------------- scratch ----------------
__device__ float  g_a[HH * DD];
__device__ float  g_c[HH];
__device__ float  g_qf[DD];
__device__ int    g_cnt32[NCPY * RNUM];   // invariant: zero at entry (scan resets)
__device__ int    g_cur32[NCPY * RNUM];
__device__ int    g_deg[RNUM];            // invariant: zero at entry (scan resets)
__device__ int    g_starts[RNUM + 1];
__device__ float  g_dis[RNUM];
__device__ int    g_idx[1 << 20];
__device__ float4 g_e4[1 << 19];          // exp-scores per POI (8 MB)
__device__ float  g_Px[RNUM * HH * DD];
__device__ float  g_hg[RNUM * DD];

// ---------------- launch 1: qf (block 0) + hist/deg (rest) ----------------
__global__ void k_hist(const float* __restrict__ S, const float* __restrict__ Wq,
                       const float* __restrict__ bq,
                       const int* __restrict__ zone, int N,
                       const int* __restrict__ edst, int E) {
    int t = threadIdx.x;
    if (blockIdx.x == 0) {
        __shared__ float sS[DD];
        if (t < DD) sS[t] = S[t];
        __syncthreads();
        if (t < DD) {
            const float4* wr = (const float4*)(Wq + t * DD);
            const float4* sv = (const float4*)sS;
            float s = 0.f;
#pragma unroll
            for (int j = 0; j < 32; j++) {
                float4 w = wr[j], v = sv[j];
                s += w.x * v.x + w.y * v.y + w.z * v.z + w.w * v.w;
            }
            g_qf[t] = s + bq[t];
        }
        return;
    }
    int i = (blockIdx.x - 1) * 256 + t;
    if (i < N) {
        int c = (i >> 8) & (NCPY - 1);
        atomicAdd(&g_cnt32[c * RNUM + zone[i]], 1);
    }
    if (i < E) atomicAdd(&g_deg[edst[i]], 1);
}

// ---------------- launch 2: block 0 = scan; blocks 1-4 = a/c per head ----------------
__global__ void k_scan(const float* __restrict__ Wk, const float* __restrict__ bk) {
    int t = threadIdx.x; // 1024
    if (blockIdx.x > 0) {
        int h = blockIdx.x - 1;                  // head
        __shared__ float sq[32];
        __shared__ float spart[8 * DD];
        if (t < 32) sq[t] = g_qf[h * 32 + t];
        __syncthreads();
        const float scale = 0.08838834764831845f; // 1/sqrt(128)
        int j = t & 127, part = t >> 7;          // 8 parts x 4 rows
        float acc = 0.f;
#pragma unroll
        for (int k = 0; k < 4; k++) {
            int dh = part * 4 + k;
            acc += sq[dh] * Wk[(h * 32 + dh) * DD + j];
        }
        spart[part * DD + j] = acc;
        __syncthreads();
        if (t < DD) {
            float s = 0.f;
#pragma unroll
            for (int p = 0; p < 8; p++) s += spart[p * DD + t];
            g_a[h * DD + t] = s * scale;
        }
        if (t == 128) {
            float s = 0.f;
#pragma unroll
            for (int dh = 0; dh < 32; dh++) s += sq[dh] * bk[h * 32 + dh];
            g_c[h] = s * scale;
        }
        return;
    }
    __shared__ int sbuf[2][2048];
    for (int k = 0; k < 2; k++) {
        int r = t + k * 1024;
        int tot = 0;
        if (r < RNUM)
            for (int c = 0; c < NCPY; c++) tot += g_cnt32[c * RNUM + r];
        sbuf[0][r] = tot;
    }
    __syncthreads();
    int src = 0;
    for (int off = 1; off < 2048; off <<= 1) {
        for (int k = 0; k < 2; k++) {
            int i = t + k * 1024;
            int v = sbuf[src][i];
            if (i >= off) v += sbuf[src][i - off];
            sbuf[1 - src][i] = v;
        }
        __syncthreads();
        src ^= 1;
    }
    for (int k = 0; k < 2; k++) {
        int r = t + k * 1024;
        if (r <= RNUM) g_starts[r] = (r == 0) ? 0 : sbuf[src][r - 1];
        if (r < RNUM) {
            int run = (r == 0) ? 0 : sbuf[src][r - 1];
            for (int c = 0; c < NCPY; c++) {
                int v = g_cnt32[c * RNUM + r];
                g_cur32[c * RNUM + r] = run;
                run += v;
                g_cnt32[c * RNUM + r] = 0;
            }
            g_dis[r] = rsqrtf((float)(g_deg[r] + 1));
            g_deg[r] = 0;
        }
    }
}

// ---------------- launch 3: scatter (blocks < SB) + coalesced exp-scores (rest) ----------------
__global__ __launch_bounds__(256) void k_scatter_scores(
    const float* __restrict__ x, const int* __restrict__ zone, int N, int SB, int GB) {
    int bid = blockIdx.x, t = threadIdx.x;
    if (bid < SB) {
        int i = bid * 256 + t;
        if (i < N) {
            int z = zone[i];
            int c = (i >> 8) & (NCPY - 1);
            int pos = atomicAdd(&g_cur32[c * RNUM + z], 1);
            g_idx[pos] = i;
        }
        return;
    }
    __shared__ __align__(16) float4 sa4[HH * 32];
    __shared__ float sc[HH];
    for (int i = t; i < HH * DD; i += 256) ((float*)sa4)[i] = g_a[i];
    if (t < HH) sc[t] = g_c[t];
    __syncthreads();

    int warp = t >> 5, lane = t & 31, sub = lane >> 3, sl = lane & 7;
    for (int chunk = bid - SB; chunk * 32 < N; chunk += GB) {
        int row = chunk * 32 + warp * 4 + sub;
        bool ok = row < N;
        int rowc = ok ? row : 0;
        const float4* xr = (const float4*)(x + (size_t)rowc * DD);
        float p0 = 0.f, p1 = 0.f, p2 = 0.f, p3 = 0.f;
#pragma unroll
        for (int k = 0; k < 4; k++) {
            float4 xv = xr[sl * 4 + k];
            float4 a0 = sa4[0 * 32 + sl * 4 + k];
            float4 a1 = sa4[1 * 32 + sl * 4 + k];
            float4 a2 = sa4[2 * 32 + sl * 4 + k];
            float4 a3 = sa4[3 * 32 + sl * 4 + k];
            p0 += xv.x * a0.x + xv.y * a0.y + xv.z * a0.z + xv.w * a0.w;
            p1 += xv.x * a1.x + xv.y * a1.y + xv.z * a1.z + xv.w * a1.w;
            p2 += xv.x * a2.x + xv.y * a2.y + xv.z * a2.z + xv.w * a2.w;
            p3 += xv.x * a3.x + xv.y * a3.y + xv.z * a3.z + xv.w * a3.w;
        }
#pragma unroll
        for (int off = 1; off < 8; off <<= 1) {
            p0 += __shfl_xor_sync(0xffffffffu, p0, off);
            p1 += __shfl_xor_sync(0xffffffffu, p1, off);
            p2 += __shfl_xor_sync(0xffffffffu, p2, off);
            p3 += __shfl_xor_sync(0xffffffffu, p3, off);
        }
        if (ok && sl == 0) {
            float4 e;
            e.x = __expf(p0 + sc[0]);
            e.y = __expf(p1 + sc[1]);
            e.z = __expf(p2 + sc[2]);
            e.w = __expf(p3 + sc[3]);
            g_e4[row] = e;
        }
    }
}

// ---------------- launch 4: region weighted-sum (warp-pair split, 2 heads/warp) ----------------
__global__ __launch_bounds__(256, 6) void k_region(const float* __restrict__ x) {
    int r = blockIdx.x;
    int base = g_starts[r];
    int cnt = g_starts[r + 1] - base;
    if (cnt > MAXM) cnt = MAXM;
    int t = threadIdx.x;

    if (cnt == 0) {
        for (int o = t; o < HH * DD; o += 256) g_Px[r * (HH * DD) + o] = 0.f;
        return;
    }

    __shared__ int   sidx[MAXM];                    // 3 KB
    __shared__ __align__(16) float4 se[MAXM];       // 12 KB
    __shared__ __align__(16) float red[8 * 2 * DD]; // 8 KB
    __shared__ float sden[8 * 2];
    __shared__ float sinv[HH];

    for (int i = t; i < cnt; i += 256) {
        int n = g_idx[base + i];
        sidx[i] = n;
        se[i] = __ldg(&g_e4[n]);
    }
    __syncthreads();

    int warp = t >> 5, lane = t & 31;
    int pr = warp & 3;
    int hp = warp >> 2;
    const float2* ep = ((const float2*)se) + hp;

    float4 acc0 = make_float4(0.f, 0.f, 0.f, 0.f), acc1 = acc0;
    float d0 = 0.f, d1 = 0.f;

    int i = pr;
    for (; i + 4 < cnt; i += 8) {
        int n0 = sidx[i], n1 = sidx[i + 4];
        float4 x0 = __ldg((const float4*)(x + (size_t)n0 * DD) + lane);
        float4 x1 = __ldg((const float4*)(x + (size_t)n1 * DD) + lane);
        float2 e0 = ep[2 * i];
        float2 e1 = ep[2 * (i + 4)];
        acc0.x += e0.x * x0.x; acc0.y += e0.x * x0.y; acc0.z += e0.x * x0.z; acc0.w += e0.x * x0.w;
        acc1.x += e0.y * x0.x; acc1.y += e0.y * x0.y; acc1.z += e0.y * x0.z; acc1.w += e0.y * x0.w;
        d0 += e0.x; d1 += e0.y;
        acc0.x += e1.x * x1.x; acc0.y += e1.x * x1.y; acc0.z += e1.x * x1.z; acc0.w += e1.x * x1.w;
        acc1.x += e1.y * x1.x; acc1.y += e1.y * x1.y; acc1.z += e1.y * x1.z; acc1.w += e1.y * x1.w;
        d0 += e1.x; d1 += e1.y;
    }
    for (; i < cnt; i += 4) {
        int n = sidx[i];
        float4 xv = __ldg((const float4*)(x + (size_t)n * DD) + lane);
        float2 e = ep[2 * i];
        acc0.x += e.x * xv.x; acc0.y += e.x * xv.y; acc0.z += e.x * xv.z; acc0.w += e.x * xv.w;
        acc1.x += e.y * xv.x; acc1.y += e.y * xv.y; acc1.z += e.y * xv.z; acc1.w += e.y * xv.w;
        d0 += e.x; d1 += e.y;
    }

    ((float4*)(red + (warp * 2 + 0) * DD))[lane] = acc0;
    ((float4*)(red + (warp * 2 + 1) * DD))[lane] = acc1;
    if (lane == 0) { sden[warp * 2 + 0] = d0; sden[warp * 2 + 1] = d1; }
    __syncthreads();

    if (t < HH) {
        int wb = (t >> 1) * 4, hh = t & 1;
        float s = sden[(wb + 0) * 2 + hh] + sden[(wb + 1) * 2 + hh]
                + sden[(wb + 2) * 2 + hh] + sden[(wb + 3) * 2 + hh];
        sinv[t] = 1.f / s;
    }
    __syncthreads();
    for (int o = t; o < HH * DD; o += 256) {
        int h = o >> 7, d = o & 127;
        int wb = (h >> 1) * 4, hh = h & 1;
        float s = red[((wb + 0) * 2 + hh) * DD + d] + red[((wb + 1) * 2 + hh) * DD + d]
                + red[((wb + 2) * 2 + hh) * DD + d] + red[((wb + 3) * 2 + hh) * DD + d];
        g_Px[r * (HH * DD) + o] = s * sinv[h];
    }
}

// ---------------- launch 5: fused dense epilogue ----------------
__global__ __launch_bounds__(512) void k_epi(
    const float* __restrict__ Wv, const float* __restrict__ bv,
    const float* __restrict__ Wo, const float* __restrict__ bo,
    const float* __restrict__ Wg, const float* __restrict__ bg,
    float* __restrict__ out) {
    int rb = blockIdx.x * 16;
    __shared__ __align__(16) float sPx[16 * 512];
    __shared__ __align__(16) float sA[16 * XST];
    __shared__ __align__(16) float sB[16 * XST];
    __shared__ float sqf[DD];
    __shared__ float sflag[16];
    int t = threadIdx.x;

    for (int i = t; i < 16 * 512; i += 512) sPx[i] = g_Px[rb * 512 + i];
    if (t < DD) sqf[t] = g_qf[t];
    if (t < 16) sflag[t] = (g_starts[rb + t + 1] > g_starts[rb + t]) ? 1.f : 0.f;
    __syncthreads();

    int d = t & 127, rg = t >> 7;
    int h = d >> 5;
    {
        const float4* wv4 = (const float4*)(Wv + d * DD);
        float o0 = 0.f, o1 = 0.f, o2 = 0.f, o3 = 0.f;
#pragma unroll 8
        for (int j = 0; j < 32; j++) {
            float4 w = wv4[j];
            float4 p0 = ((const float4*)(sPx + (rg * 4 + 0) * 512 + h * DD))[j];
            float4 p1 = ((const float4*)(sPx + (rg * 4 + 1) * 512 + h * DD))[j];
            float4 p2 = ((const float4*)(sPx + (rg * 4 + 2) * 512 + h * DD))[j];
            float4 p3 = ((const float4*)(sPx + (rg * 4 + 3) * 512 + h * DD))[j];
            o0 += w.x * p0.x + w.y * p0.y + w.z * p0.z + w.w * p0.w;
            o1 += w.x * p1.x + w.y * p1.y + w.z * p1.z + w.w * p1.w;
            o2 += w.x * p2.x + w.y * p2.y + w.z * p2.z + w.w * p2.w;
            o3 += w.x * p3.x + w.y * p3.y + w.z * p3.z + w.w * p3.w;
        }
        float bvd = bv[d], qfd = sqf[d];
        sA[(rg * 4 + 0) * XST + d] = qfd + (o0 + bvd) * sflag[rg * 4 + 0];
        sA[(rg * 4 + 1) * XST + d] = qfd + (o1 + bvd) * sflag[rg * 4 + 1];
        sA[(rg * 4 + 2) * XST + d] = qfd + (o2 + bvd) * sflag[rg * 4 + 2];
        sA[(rg * 4 + 3) * XST + d] = qfd + (o3 + bvd) * sflag[rg * 4 + 3];
    }
    __syncthreads();
    {
        const float4* wo4 = (const float4*)(Wo + d * DD);
        float o0 = 0.f, o1 = 0.f, o2 = 0.f, o3 = 0.f;
#pragma unroll 8
        for (int j = 0; j < 32; j++) {
            float4 w = wo4[j];
            float4 p0 = ((const float4*)(sA + (rg * 4 + 0) * XST))[j];
            float4 p1 = ((const float4*)(sA + (rg * 4 + 1) * XST))[j];
            float4 p2 = ((const float4*)(sA + (rg * 4 + 2) * XST))[j];
            float4 p3 = ((const float4*)(sA + (rg * 4 + 3) * XST))[j];
            o0 += w.x * p0.x + w.y * p0.y + w.z * p0.z + w.w * p0.w;
            o1 += w.x * p1.x + w.y * p1.y + w.z * p1.z + w.w * p1.w;
            o2 += w.x * p2.x + w.y * p2.y + w.z * p2.z + w.w * p2.w;
            o3 += w.x * p3.x + w.y * p3.y + w.z * p3.z + w.w * p3.w;
        }
        float bod = bo[d];
        sB[(rg * 4 + 0) * XST + d] = sA[(rg * 4 + 0) * XST + d] + fmaxf(o0 + bod, 0.f);
        sB[(rg * 4 + 1) * XST + d] = sA[(rg * 4 + 1) * XST + d] + fmaxf(o1 + bod, 0.f);
        sB[(rg * 4 + 2) * XST + d] = sA[(rg * 4 + 2) * XST + d] + fmaxf(o2 + bod, 0.f);
        sB[(rg * 4 + 3) * XST + d] = sA[(rg * 4 + 3) * XST + d] + fmaxf(o3 + bod, 0.f);
    }
    __syncthreads();
    {
        const float4* wg4 = (const float4*)(Wg + d * DD);
        float o0 = 0.f, o1 = 0.f, o2 = 0.f, o3 = 0.f;
#pragma unroll 8
        for (int j = 0; j < 32; j++) {
            float4 w = wg4[j];
            float4 p0 = ((const float4*)(sB + (rg * 4 + 0) * XST))[j];
            float4 p1 = ((const float4*)(sB + (rg * 4 + 1) * XST))[j];
            float4 p2 = ((const float4*)(sB + (rg * 4 + 2) * XST))[j];
            float4 p3 = ((const float4*)(sB + (rg * 4 + 3) * XST))[j];
            o0 += w.x * p0.x + w.y * p0.y + w.z * p0.z + w.w * p0.w;
            o1 += w.x * p1.x + w.y * p1.y + w.z * p1.z + w.w * p1.w;
            o2 += w.x * p2.x + w.y * p2.y + w.z * p2.z + w.w * p2.w;
            o3 += w.x * p3.x + w.y * p3.y + w.z * p3.z + w.w * p3.w;
        }
        float bgd = bg[d];
#pragma unroll
        for (int k = 0; k < 4; k++) {
            int rr = rg * 4 + k;
            float hg = (k == 0) ? o0 : (k == 1) ? o1 : (k == 2) ? o2 : o3;
            int r = rb + rr;
            g_hg[r * DD + d] = hg;
            float dis = g_dis[r];
            out[r * DD + d] = bgd + dis * dis * hg;
        }
    }
}

// ---------------- launches 6/7: GCN edges + PReLU ----------------
__global__ void k_gcn_edges(const int* __restrict__ src, const int* __restrict__ dst,
                            int E, float* __restrict__ out) {
    int tid = blockIdx.x * blockDim.x + threadIdx.x;
    int e = tid >> 5, lane = tid & 31;
    if (e < E) {
        int s = src[e], d = dst[e];
        float norm = g_dis[s] * g_dis[d];
        float4 hv = ((const float4*)g_hg)[s * 32 + lane];
        float* ob = out + d * DD + lane * 4;
        atomicAdd(ob + 0, norm * hv.x);
        atomicAdd(ob + 1, norm * hv.y);
        atomicAdd(ob + 2, norm * hv.z);
        atomicAdd(ob + 3, norm * hv.w);
    }
}

__global__ void k_prelu(float* __restrict__ out, const float* __restrict__ pw) {
    int i = blockIdx.x * blockDim.x + threadIdx.x;
    if (i < RNUM * DD) {
        float v = out[i];
        out[i] = (v > 0.f) ? v : pw[i & 127] * v;
    }
}

// ---------------- launch ----------------
extern "C" void kernel_launch(void* const* d_in, const int* in_sizes, int n_in,
                              void* d_out, int out_size) {
    const float* x    = (const float*)d_in[0];
    const int*   zone = (const int*)d_in[1];
    const int*   adj  = (const int*)d_in[2];
    const float* S    = (const float*)d_in[3];
    const float* Wq   = (const float*)d_in[4];
    const float* bq   = (const float*)d_in[5];
    const float* Wk   = (const float*)d_in[6];
    const float* bk   = (const float*)d_in[7];
    const float* Wv   = (const float*)d_in[8];
    const float* bv   = (const float*)d_in[9];
    const float* Wo   = (const float*)d_in[10];
    const float* bo   = (const float*)d_in[11];
    const float* Wg   = (const float*)d_in[12];
    const float* bg   = (const float*)d_in[13];
    const float* pw   = (const float*)d_in[14];
    float* out = (float*)d_out;

    int N = in_sizes[0] / DD;
    int E = in_sizes[2] / 2;
    const int* esrc = adj;
    const int* edst = adj + E;
    int NE = (N > E) ? N : E;

    int SB = (N + 255) / 256;
    int GB = 2368;

    k_hist<<<1 + (NE + 255) / 256, 256>>>(S, Wq, bq, zone, N, edst, E);
    k_scan<<<1 + HH, 1024>>>(Wk, bk);
    k_scatter_scores<<<SB + GB, 256>>>(x, zone, N, SB, GB);
    k_region<<<RNUM, 256>>>(x);
    k_epi<<<RNUM / 16, 512>>>(Wv, bv, Wo, bo, Wg, bg, out);
    k_gcn_edges<<<(E * 32 + 255) / 256, 256>>>(esrc, edst, E, out);
    k_prelu<<<(RNUM * DD + 255) / 256, 256>>>(out, pw);
}

// round 7
// speedup vs baseline: 1.3049x; 1.3049x over previous
#include <cuda_runtime.h>
#include <math_constants.h>

#define DD   128
#define HH   4
#define RNUM 2000
#define MAXM 768
#define NCPY 32
#define XST  132

// ---------------- scratch ----------------
__device__ float  g_a[HH * DD];
__device__ float  g_c[HH];
__device__ float  g_qf[DD];
__device__ int    g_cnt32[NCPY * RNUM];   // invariant: zero at entry (scan resets)
__device__ int    g_cur32[NCPY * RNUM];
__device__ int    g_deg[RNUM];            // invariant: zero at entry (scan resets)
__device__ int    g_starts[RNUM + 1];
__device__ float  g_dis[RNUM];
__device__ int    g_idx[1 << 20];
__device__ float  g_Px[RNUM * HH * DD];
__device__ float  g_hg[RNUM * DD];

// ---------------- launch 1: qf (block 0) + hist/deg (rest) ----------------
__global__ void k_hist(const float* __restrict__ S, const float* __restrict__ Wq,
                       const float* __restrict__ bq,
                       const int* __restrict__ zone, int N,
                       const int* __restrict__ edst, int E) {
    int t = threadIdx.x;
    if (blockIdx.x == 0) {
        __shared__ float sS[DD];
        if (t < DD) sS[t] = S[t];
        __syncthreads();
        if (t < DD) {
            const float4* wr = (const float4*)(Wq + t * DD);
            const float4* sv = (const float4*)sS;
            float s = 0.f;
#pragma unroll
            for (int j = 0; j < 32; j++) {
                float4 w = wr[j], v = sv[j];
                s += w.x * v.x + w.y * v.y + w.z * v.z + w.w * v.w;
            }
            g_qf[t] = s + bq[t];
        }
        return;
    }
    int i = (blockIdx.x - 1) * 256 + t;
    if (i < N) {
        int c = (i >> 8) & (NCPY - 1);
        atomicAdd(&g_cnt32[c * RNUM + zone[i]], 1);
    }
    if (i < E) atomicAdd(&g_deg[edst[i]], 1);
}

// ---------------- launch 2: block 0 = scan; blocks 1-4 = a/c per head ----------------
__global__ void k_scan(const float* __restrict__ Wk, const float* __restrict__ bk) {
    int t = threadIdx.x; // 1024
    if (blockIdx.x > 0) {
        int h = blockIdx.x - 1;
        __shared__ float sq[32];
        __shared__ float spart[8 * DD];
        if (t < 32) sq[t] = g_qf[h * 32 + t];
        __syncthreads();
        const float scale = 0.08838834764831845f; // 1/sqrt(128)
        int j = t & 127, part = t >> 7;
        float acc = 0.f;
#pragma unroll
        for (int k = 0; k < 4; k++) {
            int dh = part * 4 + k;
            acc += sq[dh] * Wk[(h * 32 + dh) * DD + j];
        }
        spart[part * DD + j] = acc;
        __syncthreads();
        if (t < DD) {
            float s = 0.f;
#pragma unroll
            for (int p = 0; p < 8; p++) s += spart[p * DD + t];
            g_a[h * DD + t] = s * scale;
        }
        if (t == 128) {
            float s = 0.f;
#pragma unroll
            for (int dh = 0; dh < 32; dh++) s += sq[dh] * bk[h * 32 + dh];
            g_c[h] = s * scale;
        }
        return;
    }
    __shared__ int sbuf[2][2048];
    for (int k = 0; k < 2; k++) {
        int r = t + k * 1024;
        int tot = 0;
        if (r < RNUM)
            for (int c = 0; c < NCPY; c++) tot += g_cnt32[c * RNUM + r];
        sbuf[0][r] = tot;
    }
    __syncthreads();
    int src = 0;
    for (int off = 1; off < 2048; off <<= 1) {
        for (int k = 0; k < 2; k++) {
            int i = t + k * 1024;
            int v = sbuf[src][i];
            if (i >= off) v += sbuf[src][i - off];
            sbuf[1 - src][i] = v;
        }
        __syncthreads();
        src ^= 1;
    }
    for (int k = 0; k < 2; k++) {
        int r = t + k * 1024;
        if (r <= RNUM) g_starts[r] = (r == 0) ? 0 : sbuf[src][r - 1];
        if (r < RNUM) {
            int run = (r == 0) ? 0 : sbuf[src][r - 1];
            for (int c = 0; c < NCPY; c++) {
                int v = g_cnt32[c * RNUM + r];
                g_cur32[c * RNUM + r] = run;
                run += v;
                g_cnt32[c * RNUM + r] = 0;
            }
            g_dis[r] = rsqrtf((float)(g_deg[r] + 1));
            g_deg[r] = 0;
        }
    }
}

// ---------------- launch 3: scatter ----------------
__global__ void k_scatter(const int* __restrict__ zone, int N) {
    int i = blockIdx.x * blockDim.x + threadIdx.x;
    if (i < N) {
        int z = zone[i];
        int c = (i >> 8) & (NCPY - 1);
        int pos = atomicAdd(&g_cur32[c * RNUM + z], 1);
        g_idx[pos] = i;
    }
}

// ---------------- launch 4: region — fused scores + weighted-sum (single x pass) ----------------
__global__ __launch_bounds__(256, 4) void k_region(const float* __restrict__ x) {
    int r = blockIdx.x;
    int base = g_starts[r];
    int cnt = g_starts[r + 1] - base;
    if (cnt > MAXM) cnt = MAXM;
    int t = threadIdx.x;

    if (cnt == 0) {
        for (int o = t; o < HH * DD; o += 256) g_Px[r * (HH * DD) + o] = 0.f;
        return;
    }

    __shared__ int   sidx[MAXM];                      // 3 KB
    __shared__ __align__(16) float4 sa4[HH * 32];     // 2 KB
    __shared__ float sc[HH];
    __shared__ __align__(16) float red[8 * HH * DD];  // 16 KB
    __shared__ float sden[8 * HH];
    __shared__ float sinv[HH];

    for (int i = t; i < HH * DD; i += 256) ((float*)sa4)[i] = g_a[i];
    if (t < HH) sc[t] = g_c[t];
    for (int i = t; i < cnt; i += 256) sidx[i] = g_idx[base + i];
    __syncthreads();

    int warp = t >> 5, lane = t & 31;
    // a vectors register-resident per lane
    float4 A0 = sa4[0 * 32 + lane];
    float4 A1 = sa4[1 * 32 + lane];
    float4 A2 = sa4[2 * 32 + lane];
    float4 A3 = sa4[3 * 32 + lane];
    float c0 = sc[0], c1 = sc[1], c2 = sc[2], c3 = sc[3];

    float4 acc0 = make_float4(0.f, 0.f, 0.f, 0.f), acc1 = acc0, acc2 = acc0, acc3 = acc0;
    float den0 = 0.f, den1 = 0.f, den2 = 0.f, den3 = 0.f;

    int i = warp;
    for (; i + 8 < cnt; i += 16) {
        int n0 = sidx[i], n1 = sidx[i + 8];
        float4 x0 = __ldg((const float4*)(x + (size_t)n0 * DD) + lane);
        float4 x1 = __ldg((const float4*)(x + (size_t)n1 * DD) + lane);
        // scores for both members (partial dots)
        float p00 = x0.x * A0.x + x0.y * A0.y + x0.z * A0.z + x0.w * A0.w;
        float p01 = x0.x * A1.x + x0.y * A1.y + x0.z * A1.z + x0.w * A1.w;
        float p02 = x0.x * A2.x + x0.y * A2.y + x0.z * A2.z + x0.w * A2.w;
        float p03 = x0.x * A3.x + x0.y * A3.y + x0.z * A3.z + x0.w * A3.w;
        float p10 = x1.x * A0.x + x1.y * A0.y + x1.z * A0.z + x1.w * A0.w;
        float p11 = x1.x * A1.x + x1.y * A1.y + x1.z * A1.z + x1.w * A1.w;
        float p12 = x1.x * A2.x + x1.y * A2.y + x1.z * A2.z + x1.w * A2.w;
        float p13 = x1.x * A3.x + x1.y * A3.y + x1.z * A3.z + x1.w * A3.w;
#pragma unroll
        for (int off = 16; off; off >>= 1) {
            p00 += __shfl_xor_sync(0xffffffffu, p00, off);
            p01 += __shfl_xor_sync(0xffffffffu, p01, off);
            p02 += __shfl_xor_sync(0xffffffffu, p02, off);
            p03 += __shfl_xor_sync(0xffffffffu, p03, off);
            p10 += __shfl_xor_sync(0xffffffffu, p10, off);
            p11 += __shfl_xor_sync(0xffffffffu, p11, off);
            p12 += __shfl_xor_sync(0xffffffffu, p12, off);
            p13 += __shfl_xor_sync(0xffffffffu, p13, off);
        }
        float e00 = __expf(p00 + c0), e01 = __expf(p01 + c1);
        float e02 = __expf(p02 + c2), e03 = __expf(p03 + c3);
        float e10 = __expf(p10 + c0), e11 = __expf(p11 + c1);
        float e12 = __expf(p12 + c2), e13 = __expf(p13 + c3);
        acc0.x += e00 * x0.x; acc0.y += e00 * x0.y; acc0.z += e00 * x0.z; acc0.w += e00 * x0.w;
        acc1.x += e01 * x0.x; acc1.y += e01 * x0.y; acc1.z += e01 * x0.z; acc1.w += e01 * x0.w;
        acc2.x += e02 * x0.x; acc2.y += e02 * x0.y; acc2.z += e02 * x0.z; acc2.w += e02 * x0.w;
        acc3.x += e03 * x0.x; acc3.y += e03 * x0.y; acc3.z += e03 * x0.z; acc3.w += e03 * x0.w;
        den0 += e00; den1 += e01; den2 += e02; den3 += e03;
        acc0.x += e10 * x1.x; acc0.y += e10 * x1.y; acc0.z += e10 * x1.z; acc0.w += e10 * x1.w;
        acc1.x += e11 * x1.x; acc1.y += e11 * x1.y; acc1.z += e11 * x1.z; acc1.w += e11 * x1.w;
        acc2.x += e12 * x1.x; acc2.y += e12 * x1.y; acc2.z += e12 * x1.z; acc2.w += e12 * x1.w;
        acc3.x += e13 * x1.x; acc3.y += e13 * x1.y; acc3.z += e13 * x1.z; acc3.w += e13 * x1.w;
        den0 += e10; den1 += e11; den2 += e12; den3 += e13;
    }
    for (; i < cnt; i += 8) {
        int n = sidx[i];
        float4 xv = __ldg((const float4*)(x + (size_t)n * DD) + lane);
        float p0 = xv.x * A0.x + xv.y * A0.y + xv.z * A0.z + xv.w * A0.w;
        float p1 = xv.x * A1.x + xv.y * A1.y + xv.z * A1.z + xv.w * A1.w;
        float p2 = xv.x * A2.x + xv.y * A2.y + xv.z * A2.z + xv.w * A2.w;
        float p3 = xv.x * A3.x + xv.y * A3.y + xv.z * A3.z + xv.w * A3.w;
#pragma unroll
        for (int off = 16; off; off >>= 1) {
            p0 += __shfl_xor_sync(0xffffffffu, p0, off);
            p1 += __shfl_xor_sync(0xffffffffu, p1, off);
            p2 += __shfl_xor_sync(0xffffffffu, p2, off);
            p3 += __shfl_xor_sync(0xffffffffu, p3, off);
        }
        float e0 = __expf(p0 + c0), e1 = __expf(p1 + c1);
        float e2 = __expf(p2 + c2), e3 = __expf(p3 + c3);
        acc0.x += e0 * xv.x; acc0.y += e0 * xv.y; acc0.z += e0 * xv.z; acc0.w += e0 * xv.w;
        acc1.x += e1 * xv.x; acc1.y += e1 * xv.y; acc1.z += e1 * xv.z; acc1.w += e1 * xv.w;
        acc2.x += e2 * xv.x; acc2.y += e2 * xv.y; acc2.z += e2 * xv.z; acc2.w += e2 * xv.w;
        acc3.x += e3 * xv.x; acc3.y += e3 * xv.y; acc3.z += e3 * xv.z; acc3.w += e3 * xv.w;
        den0 += e0; den1 += e1; den2 += e2; den3 += e3;
    }

    ((float4*)(red + (warp * HH + 0) * DD))[lane] = acc0;
    ((float4*)(red + (warp * HH + 1) * DD))[lane] = acc1;
    ((float4*)(red + (warp * HH + 2) * DD))[lane] = acc2;
    ((float4*)(red + (warp * HH + 3) * DD))[lane] = acc3;
    if (lane == 0) {
        sden[warp * HH + 0] = den0; sden[warp * HH + 1] = den1;
        sden[warp * HH + 2] = den2; sden[warp * HH + 3] = den3;
    }
    __syncthreads();
    if (t < HH) {
        float s = 0.f;
#pragma unroll
        for (int g = 0; g < 8; g++) s += sden[g * HH + t];
        sinv[t] = 1.f / s;
    }
    __syncthreads();
    for (int o = t; o < HH * DD; o += 256) {
        int h = o >> 7, d = o & 127;
        float s = 0.f;
#pragma unroll
        for (int g = 0; g < 8; g++) s += red[(g * HH + h) * DD + d];
        g_Px[r * (HH * DD) + o] = s * sinv[h];
    }
}

// ---------------- launch 5: fused dense epilogue ----------------
__global__ __launch_bounds__(512) void k_epi(
    const float* __restrict__ Wv, const float* __restrict__ bv,
    const float* __restrict__ Wo, const float* __restrict__ bo,
    const float* __restrict__ Wg, const float* __restrict__ bg,
    float* __restrict__ out) {
    int rb = blockIdx.x * 16;
    __shared__ __align__(16) float sPx[16 * 512];
    __shared__ __align__(16) float sA[16 * XST];
    __shared__ __align__(16) float sB[16 * XST];
    __shared__ float sqf[DD];
    __shared__ float sflag[16];
    int t = threadIdx.x;

    for (int i = t; i < 16 * 512; i += 512) sPx[i] = g_Px[rb * 512 + i];
    if (t < DD) sqf[t] = g_qf[t];
    if (t < 16) sflag[t] = (g_starts[rb + t + 1] > g_starts[rb + t]) ? 1.f : 0.f;
    __syncthreads();

    int d = t & 127, rg = t >> 7;
    int h = d >> 5;
    {
        const float4* wv4 = (const float4*)(Wv + d * DD);
        float o0 = 0.f, o1 = 0.f, o2 = 0.f, o3 = 0.f;
#pragma unroll 8
        for (int j = 0; j < 32; j++) {
            float4 w = wv4[j];
            float4 p0 = ((const float4*)(sPx + (rg * 4 + 0) * 512 + h * DD))[j];
            float4 p1 = ((const float4*)(sPx + (rg * 4 + 1) * 512 + h * DD))[j];
            float4 p2 = ((const float4*)(sPx + (rg * 4 + 2) * 512 + h * DD))[j];
            float4 p3 = ((const float4*)(sPx + (rg * 4 + 3) * 512 + h * DD))[j];
            o0 += w.x * p0.x + w.y * p0.y + w.z * p0.z + w.w * p0.w;
            o1 += w.x * p1.x + w.y * p1.y + w.z * p1.z + w.w * p1.w;
            o2 += w.x * p2.x + w.y * p2.y + w.z * p2.z + w.w * p2.w;
            o3 += w.x * p3.x + w.y * p3.y + w.z * p3.z + w.w * p3.w;
        }
        float bvd = bv[d], qfd = sqf[d];
        sA[(rg * 4 + 0) * XST + d] = qfd + (o0 + bvd) * sflag[rg * 4 + 0];
        sA[(rg * 4 + 1) * XST + d] = qfd + (o1 + bvd) * sflag[rg * 4 + 1];
        sA[(rg * 4 + 2) * XST + d] = qfd + (o2 + bvd) * sflag[rg * 4 + 2];
        sA[(rg * 4 + 3) * XST + d] = qfd + (o3 + bvd) * sflag[rg * 4 + 3];
    }
    __syncthreads();
    {
        const float4* wo4 = (const float4*)(Wo + d * DD);
        float o0 = 0.f, o1 = 0.f, o2 = 0.f, o3 = 0.f;
#pragma unroll 8
        for (int j = 0; j < 32; j++) {
            float4 w = wo4[j];
            float4 p0 = ((const float4*)(sA + (rg * 4 + 0) * XST))[j];
            float4 p1 = ((const float4*)(sA + (rg * 4 + 1) * XST))[j];
            float4 p2 = ((const float4*)(sA + (rg * 4 + 2) * XST))[j];
            float4 p3 = ((const float4*)(sA + (rg * 4 + 3) * XST))[j];
            o0 += w.x * p0.x + w.y * p0.y + w.z * p0.z + w.w * p0.w;
            o1 += w.x * p1.x + w.y * p1.y + w.z * p1.z + w.w * p1.w;
            o2 += w.x * p2.x + w.y * p2.y + w.z * p2.z + w.w * p2.w;
            o3 += w.x * p3.x + w.y * p3.y + w.z * p3.z + w.w * p3.w;
        }
        float bod = bo[d];
        sB[(rg * 4 + 0) * XST + d] = sA[(rg * 4 + 0) * XST + d] + fmaxf(o0 + bod, 0.f);
        sB[(rg * 4 + 1) * XST + d] = sA[(rg * 4 + 1) * XST + d] + fmaxf(o1 + bod, 0.f);
        sB[(rg * 4 + 2) * XST + d] = sA[(rg * 4 + 2) * XST + d] + fmaxf(o2 + bod, 0.f);
        sB[(rg * 4 + 3) * XST + d] = sA[(rg * 4 + 3) * XST + d] + fmaxf(o3 + bod, 0.f);
    }
    __syncthreads();
    {
        const float4* wg4 = (const float4*)(Wg + d * DD);
        float o0 = 0.f, o1 = 0.f, o2 = 0.f, o3 = 0.f;
#pragma unroll 8
        for (int j = 0; j < 32; j++) {
            float4 w = wg4[j];
            float4 p0 = ((const float4*)(sB + (rg * 4 + 0) * XST))[j];
            float4 p1 = ((const float4*)(sB + (rg * 4 + 1) * XST))[j];
            float4 p2 = ((const float4*)(sB + (rg * 4 + 2) * XST))[j];
            float4 p3 = ((const float4*)(sB + (rg * 4 + 3) * XST))[j];
            o0 += w.x * p0.x + w.y * p0.y + w.z * p0.z + w.w * p0.w;
            o1 += w.x * p1.x + w.y * p1.y + w.z * p1.z + w.w * p1.w;
            o2 += w.x * p2.x + w.y * p2.y + w.z * p2.z + w.w * p2.w;
            o3 += w.x * p3.x + w.y * p3.y + w.z * p3.z + w.w * p3.w;
        }
        float bgd = bg[d];
#pragma unroll
        for (int k = 0; k < 4; k++) {
            int rr = rg * 4 + k;
            float hg = (k == 0) ? o0 : (k == 1) ? o1 : (k == 2) ? o2 : o3;
            int r = rb + rr;
            g_hg[r * DD + d] = hg;
            float dis = g_dis[r];
            out[r * DD + d] = bgd + dis * dis * hg;
        }
    }
}

// ---------------- launches 6/7: GCN edges + PReLU ----------------
__global__ void k_gcn_edges(const int* __restrict__ src, const int* __restrict__ dst,
                            int E, float* __restrict__ out) {
    int tid = blockIdx.x * blockDim.x + threadIdx.x;
    int e = tid >> 5, lane = tid & 31;
    if (e < E) {
        int s = src[e], d = dst[e];
        float norm = g_dis[s] * g_dis[d];
        float4 hv = ((const float4*)g_hg)[s * 32 + lane];
        float* ob = out + d * DD + lane * 4;
        atomicAdd(ob + 0, norm * hv.x);
        atomicAdd(ob + 1, norm * hv.y);
        atomicAdd(ob + 2, norm * hv.z);
        atomicAdd(ob + 3, norm * hv.w);
    }
}

__global__ void k_prelu(float* __restrict__ out, const float* __restrict__ pw) {
    int i = blockIdx.x * blockDim.x + threadIdx.x;
    if (i < RNUM * DD) {
        float v = out[i];
        out[i] = (v > 0.f) ? v : pw[i & 127] * v;
    }
}

// ---------------- launch ----------------
extern "C" void kernel_launch(void* const* d_in, const int* in_sizes, int n_in,
                              void* d_out, int out_size) {
    const float* x    = (const float*)d_in[0];
    const int*   zone = (const int*)d_in[1];
    const int*   adj  = (const int*)d_in[2];
    const float* S    = (const float*)d_in[3];
    const float* Wq   = (const float*)d_in[4];
    const float* bq   = (const float*)d_in[5];
    const float* Wk   = (const float*)d_in[6];
    const float* bk   = (const float*)d_in[7];
    const float* Wv   = (const float*)d_in[8];
    const float* bv   = (const float*)d_in[9];
    const float* Wo   = (const float*)d_in[10];
    const float* bo   = (const float*)d_in[11];
    const float* Wg   = (const float*)d_in[12];
    const float* bg   = (const float*)d_in[13];
    const float* pw   = (const float*)d_in[14];
    float* out = (float*)d_out;

    int N = in_sizes[0] / DD;
    int E = in_sizes[2] / 2;
    const int* esrc = adj;
    const int* edst = adj + E;
    int NE = (N > E) ? N : E;

    k_hist<<<1 + (NE + 255) / 256, 256>>>(S, Wq, bq, zone, N, edst, E);
    k_scan<<<1 + HH, 1024>>>(Wk, bk);
    k_scatter<<<(N + 255) / 256, 256>>>(zone, N);
    k_region<<<RNUM, 256>>>(x);
    k_epi<<<RNUM / 16, 512>>>(Wv, bv, Wo, bo, Wg, bg, out);
    k_gcn_edges<<<(E * 32 + 255) / 256, 256>>>(esrc, edst, E, out);
    k_prelu<<<(RNUM * DD + 255) / 256, 256>>>(out, pw);
}

// round 10
// speedup vs baseline: 1.3191x; 1.0109x over previous
#include <cuda_runtime.h>
#include <math_constants.h>

#define DD   128
#define HH   4
#define RNUM 2000
#define MAXM 768
#define NCPY 32
#define XST  132

// ---------------- scratch ----------------
__device__ float  g_a[HH * DD];
__device__ float  g_c[HH];
__device__ float  g_qf[DD];
__device__ int    g_cnt32[NCPY * RNUM];   // invariant: zero at entry (scan resets)
__device__ int    g_cur32[NCPY * RNUM];
__device__ int    g_deg[RNUM];            // invariant: zero at entry (scan resets)
__device__ int    g_starts[RNUM + 1];
__device__ float  g_dis[RNUM];
__device__ int    g_idx[1 << 20];
__device__ float  g_Px[RNUM * HH * DD];
__device__ float  g_hg[RNUM * DD];

// ---------------- launch 1: qf (block 0) + hist/deg (rest) ----------------
__global__ void k_hist(const float* __restrict__ S, const float* __restrict__ Wq,
                       const float* __restrict__ bq,
                       const int* __restrict__ zone, int N,
                       const int* __restrict__ edst, int E) {
    int t = threadIdx.x;
    if (blockIdx.x == 0) {
        __shared__ float sS[DD];
        if (t < DD) sS[t] = S[t];
        __syncthreads();
        if (t < DD) {
            const float4* wr = (const float4*)(Wq + t * DD);
            const float4* sv = (const float4*)sS;
            float s = 0.f;
#pragma unroll
            for (int j = 0; j < 32; j++) {
                float4 w = wr[j], v = sv[j];
                s += w.x * v.x + w.y * v.y + w.z * v.z + w.w * v.w;
            }
            g_qf[t] = s + bq[t];
        }
        return;
    }
    int i = (blockIdx.x - 1) * 256 + t;
    if (i < N) {
        int c = (i >> 8) & (NCPY - 1);
        atomicAdd(&g_cnt32[c * RNUM + zone[i]], 1);
    }
    if (i < E) atomicAdd(&g_deg[edst[i]], 1);
}

// ---------------- launch 2: block 0 = scan; blocks 1-4 = a/c per head ----------------
__global__ void k_scan(const float* __restrict__ Wk, const float* __restrict__ bk) {
    int t = threadIdx.x; // 1024
    if (blockIdx.x > 0) {
        int h = blockIdx.x - 1;
        __shared__ float sq[32];
        __shared__ float spart[8 * DD];
        if (t < 32) sq[t] = g_qf[h * 32 + t];
        __syncthreads();
        const float scale = 0.08838834764831845f; // 1/sqrt(128)
        int j = t & 127, part = t >> 7;
        float acc = 0.f;
#pragma unroll
        for (int k = 0; k < 4; k++) {
            int dh = part * 4 + k;
            acc += sq[dh] * Wk[(h * 32 + dh) * DD + j];
        }
        spart[part * DD + j] = acc;
        __syncthreads();
        if (t < DD) {
            float s = 0.f;
#pragma unroll
            for (int p = 0; p < 8; p++) s += spart[p * DD + t];
            g_a[h * DD + t] = s * scale;
        }
        if (t == 128) {
            float s = 0.f;
#pragma unroll
            for (int dh = 0; dh < 32; dh++) s += sq[dh] * bk[h * 32 + dh];
            g_c[h] = s * scale;
        }
        return;
    }
    __shared__ int sbuf[2][2048];
    for (int k = 0; k < 2; k++) {
        int r = t + k * 1024;
        int tot = 0;
        if (r < RNUM)
            for (int c = 0; c < NCPY; c++) tot += g_cnt32[c * RNUM + r];
        sbuf[0][r] = tot;
    }
    __syncthreads();
    int src = 0;
    for (int off = 1; off < 2048; off <<= 1) {
        for (int k = 0; k < 2; k++) {
            int i = t + k * 1024;
            int v = sbuf[src][i];
            if (i >= off) v += sbuf[src][i - off];
            sbuf[1 - src][i] = v;
        }
        __syncthreads();
        src ^= 1;
    }
    for (int k = 0; k < 2; k++) {
        int r = t + k * 1024;
        if (r <= RNUM) g_starts[r] = (r == 0) ? 0 : sbuf[src][r - 1];
        if (r < RNUM) {
            int run = (r == 0) ? 0 : sbuf[src][r - 1];
            for (int c = 0; c < NCPY; c++) {
                int v = g_cnt32[c * RNUM + r];
                g_cur32[c * RNUM + r] = run;
                run += v;
                g_cnt32[c * RNUM + r] = 0;
            }
            g_dis[r] = rsqrtf((float)(g_deg[r] + 1));
            g_deg[r] = 0;
        }
    }
}

// ---------------- launch 3: scatter ----------------
__global__ void k_scatter(const int* __restrict__ zone, int N) {
    int i = blockIdx.x * blockDim.x + threadIdx.x;
    if (i < N) {
        int z = zone[i];
        int c = (i >> 8) & (NCPY - 1);
        int pos = atomicAdd(&g_cur32[c * RNUM + z], 1);
        g_idx[pos] = i;
    }
}

// ---------------- launch 4: region — fused scores + weighted-sum, interleaved reduce ----------------
__global__ __launch_bounds__(256, 4) void k_region(const float* __restrict__ x) {
    int r = blockIdx.x;
    int base = g_starts[r];
    int cnt = g_starts[r + 1] - base;
    if (cnt > MAXM) cnt = MAXM;
    int t = threadIdx.x;

    if (cnt == 0) {
        for (int o = t; o < HH * DD; o += 256) g_Px[r * (HH * DD) + o] = 0.f;
        return;
    }

    __shared__ int   sidx[MAXM];                      // 3 KB
    __shared__ __align__(16) float4 sa4[HH * 32];     // 2 KB
    __shared__ float sc[HH];
    __shared__ __align__(16) float red[8 * HH * DD];  // 16 KB
    __shared__ float sden[8 * HH];
    __shared__ float sinv[HH];

    for (int i = t; i < HH * DD; i += 256) ((float*)sa4)[i] = g_a[i];
    if (t < HH) sc[t] = g_c[t];
    for (int i = t; i < cnt; i += 256) sidx[i] = g_idx[base + i];
    __syncthreads();

    int warp = t >> 5, lane = t & 31;
    float4 A0 = sa4[0 * 32 + lane];
    float4 A1 = sa4[1 * 32 + lane];
    float4 A2 = sa4[2 * 32 + lane];
    float4 A3 = sa4[3 * 32 + lane];
    float c0 = sc[0], c1 = sc[1], c2 = sc[2], c3 = sc[3];

    int idx = lane >> 2;            // value index this lane finalizes (0..7)
    int hsel = idx & 3;
    float cv = (hsel == 0) ? c0 : (hsel == 1) ? c1 : (hsel == 2) ? c2 : c3;

    float4 acc0 = make_float4(0.f, 0.f, 0.f, 0.f), acc1 = acc0, acc2 = acc0, acc3 = acc0;
    float den0 = 0.f, den1 = 0.f, den2 = 0.f, den3 = 0.f;
    const unsigned FM = 0xffffffffu;

    int i = warp;
    for (; i + 8 < cnt; i += 16) {
        int n0 = sidx[i], n1 = sidx[i + 8];
        float4 x0 = __ldg((const float4*)(x + (size_t)n0 * DD) + lane);
        float4 x1 = __ldg((const float4*)(x + (size_t)n1 * DD) + lane);
        float p0 = x0.x * A0.x + x0.y * A0.y + x0.z * A0.z + x0.w * A0.w;
        float p1 = x0.x * A1.x + x0.y * A1.y + x0.z * A1.z + x0.w * A1.w;
        float p2 = x0.x * A2.x + x0.y * A2.y + x0.z * A2.z + x0.w * A2.w;
        float p3 = x0.x * A3.x + x0.y * A3.y + x0.z * A3.z + x0.w * A3.w;
        float p4 = x1.x * A0.x + x1.y * A0.y + x1.z * A0.z + x1.w * A0.w;
        float p5 = x1.x * A1.x + x1.y * A1.y + x1.z * A1.z + x1.w * A1.w;
        float p6 = x1.x * A2.x + x1.y * A2.y + x1.z * A2.z + x1.w * A2.w;
        float p7 = x1.x * A3.x + x1.y * A3.y + x1.z * A3.z + x1.w * A3.w;
        // stage 1: 3 butterfly stages on all 8 values -> residue-class partials (l&3)
#pragma unroll
        for (int off = 16; off >= 4; off >>= 1) {
            p0 += __shfl_xor_sync(FM, p0, off);
            p1 += __shfl_xor_sync(FM, p1, off);
            p2 += __shfl_xor_sync(FM, p2, off);
            p3 += __shfl_xor_sync(FM, p3, off);
            p4 += __shfl_xor_sync(FM, p4, off);
            p5 += __shfl_xor_sync(FM, p5, off);
            p6 += __shfl_xor_sync(FM, p6, off);
            p7 += __shfl_xor_sync(FM, p7, off);
        }
        // transpose by selection: lane finalizes value idx = lane>>2
        float v = (idx == 0) ? p0 : (idx == 1) ? p1 : (idx == 2) ? p2 : (idx == 3) ? p3
                : (idx == 4) ? p4 : (idx == 5) ? p5 : (idx == 6) ? p6 : p7;
        v += __shfl_xor_sync(FM, v, 1);
        v += __shfl_xor_sync(FM, v, 2);
        float e = __expf(v + cv);   // 1 MUFU for all 8 values
        float e00 = __shfl_sync(FM, e, 0);
        float e01 = __shfl_sync(FM, e, 4);
        float e02 = __shfl_sync(FM, e, 8);
        float e03 = __shfl_sync(FM, e, 12);
        float e10 = __shfl_sync(FM, e, 16);
        float e11 = __shfl_sync(FM, e, 20);
        float e12 = __shfl_sync(FM, e, 24);
        float e13 = __shfl_sync(FM, e, 28);
        acc0.x += e00 * x0.x; acc0.y += e00 * x0.y; acc0.z += e00 * x0.z; acc0.w += e00 * x0.w;
        acc1.x += e01 * x0.x; acc1.y += e01 * x0.y; acc1.z += e01 * x0.z; acc1.w += e01 * x0.w;
        acc2.x += e02 * x0.x; acc2.y += e02 * x0.y; acc2.z += e02 * x0.z; acc2.w += e02 * x0.w;
        acc3.x += e03 * x0.x; acc3.y += e03 * x0.y; acc3.z += e03 * x0.z; acc3.w += e03 * x0.w;
        den0 += e00; den1 += e01; den2 += e02; den3 += e03;
        acc0.x += e10 * x1.x; acc0.y += e10 * x1.y; acc0.z += e10 * x1.z; acc0.w += e10 * x1.w;
        acc1.x += e11 * x1.x; acc1.y += e11 * x1.y; acc1.z += e11 * x1.z; acc1.w += e11 * x1.w;
        acc2.x += e12 * x1.x; acc2.y += e12 * x1.y; acc2.z += e12 * x1.z; acc2.w += e12 * x1.w;
        acc3.x += e13 * x1.x; acc3.y += e13 * x1.y; acc3.z += e13 * x1.z; acc3.w += e13 * x1.w;
        den0 += e10; den1 += e11; den2 += e12; den3 += e13;
    }
    for (; i < cnt; i += 8) {
        int n = sidx[i];
        float4 xv = __ldg((const float4*)(x + (size_t)n * DD) + lane);
        float p0 = xv.x * A0.x + xv.y * A0.y + xv.z * A0.z + xv.w * A0.w;
        float p1 = xv.x * A1.x + xv.y * A1.y + xv.z * A1.z + xv.w * A1.w;
        float p2 = xv.x * A2.x + xv.y * A2.y + xv.z * A2.z + xv.w * A2.w;
        float p3 = xv.x * A3.x + xv.y * A3.y + xv.z * A3.z + xv.w * A3.w;
#pragma unroll
        for (int off = 16; off >= 4; off >>= 1) {
            p0 += __shfl_xor_sync(FM, p0, off);
            p1 += __shfl_xor_sync(FM, p1, off);
            p2 += __shfl_xor_sync(FM, p2, off);
            p3 += __shfl_xor_sync(FM, p3, off);
        }
        float v = (hsel == 0) ? p0 : (hsel == 1) ? p1 : (hsel == 2) ? p2 : p3;
        v += __shfl_xor_sync(FM, v, 1);
        v += __shfl_xor_sync(FM, v, 2);
        float e = __expf(v + cv);
        float e0 = __shfl_sync(FM, e, 0);
        float e1 = __shfl_sync(FM, e, 4);
        float e2 = __shfl_sync(FM, e, 8);
        float e3 = __shfl_sync(FM, e, 12);
        acc0.x += e0 * xv.x; acc0.y += e0 * xv.y; acc0.z += e0 * xv.z; acc0.w += e0 * xv.w;
        acc1.x += e1 * xv.x; acc1.y += e1 * xv.y; acc1.z += e1 * xv.z; acc1.w += e1 * xv.w;
        acc2.x += e2 * xv.x; acc2.y += e2 * xv.y; acc2.z += e2 * xv.z; acc2.w += e2 * xv.w;
        acc3.x += e3 * xv.x; acc3.y += e3 * xv.y; acc3.z += e3 * xv.z; acc3.w += e3 * xv.w;
        den0 += e0; den1 += e1; den2 += e2; den3 += e3;
    }

    ((float4*)(red + (warp * HH + 0) * DD))[lane] = acc0;
    ((float4*)(red + (warp * HH + 1) * DD))[lane] = acc1;
    ((float4*)(red + (warp * HH + 2) * DD))[lane] = acc2;
    ((float4*)(red + (warp * HH + 3) * DD))[lane] = acc3;
    if (lane == 0) {
        sden[warp * HH + 0] = den0; sden[warp * HH + 1] = den1;
        sden[warp * HH + 2] = den2; sden[warp * HH + 3] = den3;
    }
    __syncthreads();
    if (t < HH) {
        float s = 0.f;
#pragma unroll
        for (int g = 0; g < 8; g++) s += sden[g * HH + t];
        sinv[t] = 1.f / s;
    }
    __syncthreads();
    for (int o = t; o < HH * DD; o += 256) {
        int h = o >> 7, d = o & 127;
        float s = 0.f;
#pragma unroll
        for (int g = 0; g < 8; g++) s += red[(g * HH + h) * DD + d];
        g_Px[r * (HH * DD) + o] = s * sinv[h];
    }
}

// ---------------- launch 5: fused dense epilogue ----------------
__global__ __launch_bounds__(512) void k_epi(
    const float* __restrict__ Wv, const float* __restrict__ bv,
    const float* __restrict__ Wo, const float* __restrict__ bo,
    const float* __restrict__ Wg, const float* __restrict__ bg,
    float* __restrict__ out) {
    int rb = blockIdx.x * 16;
    __shared__ __align__(16) float sPx[16 * 512];
    __shared__ __align__(16) float sA[16 * XST];
    __shared__ __align__(16) float sB[16 * XST];
    __shared__ float sqf[DD];
    __shared__ float sflag[16];
    int t = threadIdx.x;

    for (int i = t; i < 16 * 512; i += 512) sPx[i] = g_Px[rb * 512 + i];
    if (t < DD) sqf[t] = g_qf[t];
    if (t < 16) sflag[t] = (g_starts[rb + t + 1] > g_starts[rb + t]) ? 1.f : 0.f;
    __syncthreads();

    int d = t & 127, rg = t >> 7;
    int h = d >> 5;
    {
        const float4* wv4 = (const float4*)(Wv + d * DD);
        float o0 = 0.f, o1 = 0.f, o2 = 0.f, o3 = 0.f;
#pragma unroll 8
        for (int j = 0; j < 32; j++) {
            float4 w = wv4[j];
            float4 p0 = ((const float4*)(sPx + (rg * 4 + 0) * 512 + h * DD))[j];
            float4 p1 = ((const float4*)(sPx + (rg * 4 + 1) * 512 + h * DD))[j];
            float4 p2 = ((const float4*)(sPx + (rg * 4 + 2) * 512 + h * DD))[j];
            float4 p3 = ((const float4*)(sPx + (rg * 4 + 3) * 512 + h * DD))[j];
            o0 += w.x * p0.x + w.y * p0.y + w.z * p0.z + w.w * p0.w;
            o1 += w.x * p1.x + w.y * p1.y + w.z * p1.z + w.w * p1.w;
            o2 += w.x * p2.x + w.y * p2.y + w.z * p2.z + w.w * p2.w;
            o3 += w.x * p3.x + w.y * p3.y + w.z * p3.z + w.w * p3.w;
        }
        float bvd = bv[d], qfd = sqf[d];
        sA[(rg * 4 + 0) * XST + d] = qfd + (o0 + bvd) * sflag[rg * 4 + 0];
        sA[(rg * 4 + 1) * XST + d] = qfd + (o1 + bvd) * sflag[rg * 4 + 1];
        sA[(rg * 4 + 2) * XST + d] = qfd + (o2 + bvd) * sflag[rg * 4 + 2];
        sA[(rg * 4 + 3) * XST + d] = qfd + (o3 + bvd) * sflag[rg * 4 + 3];
    }
    __syncthreads();
    {
        const float4* wo4 = (const float4*)(Wo + d * DD);
        float o0 = 0.f, o1 = 0.f, o2 = 0.f, o3 = 0.f;
#pragma unroll 8
        for (int j = 0; j < 32; j++) {
            float4 w = wo4[j];
            float4 p0 = ((const float4*)(sA + (rg * 4 + 0) * XST))[j];
            float4 p1 = ((const float4*)(sA + (rg * 4 + 1) * XST))[j];
            float4 p2 = ((const float4*)(sA + (rg * 4 + 2) * XST))[j];
            float4 p3 = ((const float4*)(sA + (rg * 4 + 3) * XST))[j];
            o0 += w.x * p0.x + w.y * p0.y + w.z * p0.z + w.w * p0.w;
            o1 += w.x * p1.x + w.y * p1.y + w.z * p1.z + w.w * p1.w;
            o2 += w.x * p2.x + w.y * p2.y + w.z * p2.z + w.w * p2.w;
            o3 += w.x * p3.x + w.y * p3.y + w.z * p3.z + w.w * p3.w;
        }
        float bod = bo[d];
        sB[(rg * 4 + 0) * XST + d] = sA[(rg * 4 + 0) * XST + d] + fmaxf(o0 + bod, 0.f);
        sB[(rg * 4 + 1) * XST + d] = sA[(rg * 4 + 1) * XST + d] + fmaxf(o1 + bod, 0.f);
        sB[(rg * 4 + 2) * XST + d] = sA[(rg * 4 + 2) * XST + d] + fmaxf(o2 + bod, 0.f);
        sB[(rg * 4 + 3) * XST + d] = sA[(rg * 4 + 3) * XST + d] + fmaxf(o3 + bod, 0.f);
    }
    __syncthreads();
    {
        const float4* wg4 = (const float4*)(Wg + d * DD);
        float o0 = 0.f, o1 = 0.f, o2 = 0.f, o3 = 0.f;
#pragma unroll 8
        for (int j = 0; j < 32; j++) {
            float4 w = wg4[j];
            float4 p0 = ((const float4*)(sB + (rg * 4 + 0) * XST))[j];
            float4 p1 = ((const float4*)(sB + (rg * 4 + 1) * XST))[j];
            float4 p2 = ((const float4*)(sB + (rg * 4 + 2) * XST))[j];
            float4 p3 = ((const float4*)(sB + (rg * 4 + 3) * XST))[j];
            o0 += w.x * p0.x + w.y * p0.y + w.z * p0.z + w.w * p0.w;
            o1 += w.x * p1.x + w.y * p1.y + w.z * p1.z + w.w * p1.w;
            o2 += w.x * p2.x + w.y * p2.y + w.z * p2.z + w.w * p2.w;
            o3 += w.x * p3.x + w.y * p3.y + w.z * p3.z + w.w * p3.w;
        }
        float bgd = bg[d];
#pragma unroll
        for (int k = 0; k < 4; k++) {
            int rr = rg * 4 + k;
            float hg = (k == 0) ? o0 : (k == 1) ? o1 : (k == 2) ? o2 : o3;
            int r = rb + rr;
            g_hg[r * DD + d] = hg;
            float dis = g_dis[r];
            out[r * DD + d] = bgd + dis * dis * hg;
        }
    }
}

// ---------------- launches 6/7: GCN edges + PReLU ----------------
__global__ void k_gcn_edges(const int* __restrict__ src, const int* __restrict__ dst,
                            int E, float* __restrict__ out) {
    int tid = blockIdx.x * blockDim.x + threadIdx.x;
    int e = tid >> 5, lane = tid & 31;
    if (e < E) {
        int s = src[e], d = dst[e];
        float norm = g_dis[s] * g_dis[d];
        float4 hv = ((const float4*)g_hg)[s * 32 + lane];
        float* ob = out + d * DD + lane * 4;
        atomicAdd(ob + 0, norm * hv.x);
        atomicAdd(ob + 1, norm * hv.y);
        atomicAdd(ob + 2, norm * hv.z);
        atomicAdd(ob + 3, norm * hv.w);
    }
}

__global__ void k_prelu(float* __restrict__ out, const float* __restrict__ pw) {
    int i = blockIdx.x * blockDim.x + threadIdx.x;
    if (i < RNUM * DD) {
        float v = out[i];
        out[i] = (v > 0.f) ? v : pw[i & 127] * v;
    }
}

// ---------------- launch ----------------
extern "C" void kernel_launch(void* const* d_in, const int* in_sizes, int n_in,
                              void* d_out, int out_size) {
    const float* x    = (const float*)d_in[0];
    const int*   zone = (const int*)d_in[1];
    const int*   adj  = (const int*)d_in[2];
    const float* S    = (const float*)d_in[3];
    const float* Wq   = (const float*)d_in[4];
    const float* bq   = (const float*)d_in[5];
    const float* Wk   = (const float*)d_in[6];
    const float* bk   = (const float*)d_in[7];
    const float* Wv   = (const float*)d_in[8];
    const float* bv   = (const float*)d_in[9];
    const float* Wo   = (const float*)d_in[10];
    const float* bo   = (const float*)d_in[11];
    const float* Wg   = (const float*)d_in[12];
    const float* bg   = (const float*)d_in[13];
    const float* pw   = (const float*)d_in[14];
    float* out = (float*)d_out;

    int N = in_sizes[0] / DD;
    int E = in_sizes[2] / 2;
    const int* esrc = adj;
    const int* edst = adj + E;
    int NE = (N > E) ? N : E;

    k_hist<<<1 + (NE + 255) / 256, 256>>>(S, Wq, bq, zone, N, edst, E);
    k_scan<<<1 + HH, 1024>>>(Wk, bk);
    k_scatter<<<(N + 255) / 256, 256>>>(zone, N);
    k_region<<<RNUM, 256>>>(x);
    k_epi<<<RNUM / 16, 512>>>(Wv, bv, Wo, bo, Wg, bg, out);
    k_gcn_edges<<<(E * 32 + 255) / 256, 256>>>(esrc, edst, E, out);
    k_prelu<<<(RNUM * DD + 255) / 256, 256>>>(out, pw);
}